// round 14
// baseline (speedup 1.0000x reference)
#include <cuda_runtime.h>
#include <cuda_bf16.h>
#include <cuda_fp16.h>
#include <cstdint>

#define N_NODES 40000
#define N_EDGES 640000
#define D 128

typedef unsigned short ushort_t;

// ---------------- scratch (device globals: no allocations allowed) ----------
static __device__ ushort_t g_XH [N_NODES * D];   // x pre-split bf16 hi
static __device__ ushort_t g_XL [N_NODES * D];   // x pre-split bf16 lo
static __device__ ushort_t g_H1H[N_NODES * D];   // hidden (msg then upd) hi
static __device__ ushort_t g_H1L[N_NODES * D];   // hidden lo
static __device__ ushort_t g_AGH[N_NODES * D];   // AGG hi
static __device__ ushort_t g_AGL[N_NODES * D];   // AGG lo
static __device__ __half   g_Y  [N_NODES * D];   // message output (fp16, for gather)
static __device__ float    g_U2 [N_NODES * D];   // pre-LN update output
static __device__ int      g_ROW[N_NODES + 1];   // CSR row offsets (by dst)
static __device__ int      g_CUR[N_NODES];       // counts, then fill cursors
static __device__ int      g_EIDX[N_EDGES];      // src ids grouped by dst
static __device__ int      g_BSUM[64];           // block sums for scan
static __device__ int      g_is64;               // edge_index dtype flag
// pre-split weights (bf16 hi / lo), [n][k] row-major:
//   Wm1 @ 0 (16384), Wm2 @ 16384, Wu1 @ 32768 (32768), Wu2 @ 65536
static __device__ ushort_t g_Wh[81920];
static __device__ ushort_t g_Wl[81920];

// ---------------- helpers ----------------------------------------------------
__device__ __forceinline__ uint32_t smem_u32(const void* p) {
    return (uint32_t)__cvta_generic_to_shared(p);
}

// split 4 fp32 -> bf16 hi (truncate) pairs + bf16 lo (rn of residual) pairs
__device__ __forceinline__ void split4(float4 v, uint32_t& h01, uint32_t& h23,
                                       uint32_t& l01, uint32_t& l23) {
    uint32_t u0 = __float_as_uint(v.x), u1 = __float_as_uint(v.y);
    uint32_t u2 = __float_as_uint(v.z), u3 = __float_as_uint(v.w);
    asm("prmt.b32 %0, %1, %2, 0x7632;" : "=r"(h01) : "r"(u0), "r"(u1));
    asm("prmt.b32 %0, %1, %2, 0x7632;" : "=r"(h23) : "r"(u2), "r"(u3));
    float lo0 = v.x - __uint_as_float(u0 & 0xFFFF0000u);
    float lo1 = v.y - __uint_as_float(u1 & 0xFFFF0000u);
    float lo2 = v.z - __uint_as_float(u2 & 0xFFFF0000u);
    float lo3 = v.w - __uint_as_float(u3 & 0xFFFF0000u);
    asm("cvt.rn.bf16x2.f32 %0, %1, %2;" : "=r"(l01) : "f"(lo1), "f"(lo0));
    asm("cvt.rn.bf16x2.f32 %0, %1, %2;" : "=r"(l23) : "f"(lo3), "f"(lo2));
}
// split 2 fp32 -> one hi u32 + one lo u32 (packed pairs)
__device__ __forceinline__ void split2(float f0, float f1, uint32_t& h01, uint32_t& l01) {
    uint32_t u0 = __float_as_uint(f0), u1 = __float_as_uint(f1);
    asm("prmt.b32 %0, %1, %2, 0x7632;" : "=r"(h01) : "r"(u0), "r"(u1));
    float r0 = f0 - __uint_as_float(u0 & 0xFFFF0000u);
    float r1 = f1 - __uint_as_float(u1 & 0xFFFF0000u);
    asm("cvt.rn.bf16x2.f32 %0, %1, %2;" : "=r"(l01) : "f"(r1), "f"(r0));
}

#define LDSM_X4(r0, r1, r2, r3, addr) \
    asm volatile("ldmatrix.sync.aligned.m8n8.x4.shared.b16 {%0,%1,%2,%3}, [%4];" \
        : "=r"(r0), "=r"(r1), "=r"(r2), "=r"(r3) : "r"(addr))

#define MMA_BF16(c, a, b) \
    asm volatile("mma.sync.aligned.m16n8k16.row.col.f32.bf16.bf16.f32 " \
        "{%0,%1,%2,%3}, {%4,%5,%6,%7}, {%8,%9}, {%0,%1,%2,%3};" \
        : "+f"((c)[0]), "+f"((c)[1]), "+f"((c)[2]), "+f"((c)[3]) \
        : "r"((a)[0]), "r"((a)[1]), "r"((a)[2]), "r"((a)[3]), \
          "r"((b)[0]), "r"((b)[1]))

// ---------------- N=64-tile GEMM, pre-split A, occupancy 3 CTAs/SM ----------
// C[:, n0:n0+64] = act(concat(A0,A1) @ W^T + bias)[:, n0:n0+64]
// All operands already bf16 hi/lo in global: A-load is a pure uint4 copy.
// OUTMODE: 0 = fp32 Cf, 1 = fp16 Ch, 2 = split hi/lo to Ohi/Olo.
template <int KT, bool RELU, int OUTMODE>
__global__ __launch_bounds__(256, 3)
void gemm64(const ushort_t* __restrict__ Ah0, const ushort_t* __restrict__ Al0,
            const ushort_t* __restrict__ Ah1, const ushort_t* __restrict__ Al1,
            int woff, const float* __restrict__ bias,
            float* __restrict__ Cf, __half* __restrict__ Ch,
            ushort_t* __restrict__ Ohi, ushort_t* __restrict__ Olo)
{
    extern __shared__ char smc[];
    float* sbias = (float*)smc;                               // 64 floats
    ushort_t* sAhi = (ushort_t*)(smc + 512);                  // [64][136]
    ushort_t* sAlo = sAhi + 64 * 136;
    ushort_t* sBhi = sAlo + 64 * 136;                         // [64][136]
    ushort_t* sBlo = sBhi + 64 * 136;

    const int tid  = threadIdx.x;
    const int lane = tid & 31;
    const int wid  = tid >> 5;
    const int wm   = (wid >> 2) * 32;        // 0 / 32
    const int wn   = (wid & 3) * 16;         // 0/16/32/48
    const int m0   = (blockIdx.x >> 1) * 64;
    const int n0   = (blockIdx.x & 1) * 64;

    if (tid < 64) sbias[tid] = bias[n0 + tid];

    float c[2][2][4];
    #pragma unroll
    for (int i = 0; i < 2; i++)
        #pragma unroll
        for (int j = 0; j < 2; j++)
            #pragma unroll
            for (int q = 0; q < 4; q++) c[i][j][q] = 0.0f;

    const int a_row = lane & 15, a_kh = (lane >> 4) * 8;
    const int b_row = (lane >> 4) * 8 + (lane & 7);
    const int b_kh  = ((lane >> 3) & 1) * 8;

    const int nchunks = KT / 128;
    for (int kc = 0; kc < nchunks; ++kc) {
        const ushort_t* Ah = (kc == 0) ? Ah0 : Ah1;
        const ushort_t* Al = (kc == 0) ? Al0 : Al1;

        // A tile: pure copy of pre-split rows m0..m0+63 (1024 uint4 per buf)
        #pragma unroll
        for (int it = 0; it < 4; ++it) {
            int idx = tid + it * 256;
            int row = idx >> 4;
            int c8  = idx & 15;
            size_t gsrc = (size_t)(m0 + row) * D + c8 * 8;
            *reinterpret_cast<uint4*>(sAhi + row * 136 + c8 * 8) =
                *reinterpret_cast<const uint4*>(Ah + gsrc);
            *reinterpret_cast<uint4*>(sAlo + row * 136 + c8 * 8) =
                *reinterpret_cast<const uint4*>(Al + gsrc);
        }
        // B tile: pre-split weights, rows n0..n0+63
        #pragma unroll
        for (int it = 0; it < 4; ++it) {
            int idx = tid + it * 256;
            int row = idx >> 4;
            int c8  = idx & 15;
            size_t gsrc = (size_t)woff + (size_t)(n0 + row) * KT + kc * 128 + c8 * 8;
            *reinterpret_cast<uint4*>(sBhi + row * 136 + c8 * 8) =
                *reinterpret_cast<const uint4*>(g_Wh + gsrc);
            *reinterpret_cast<uint4*>(sBlo + row * 136 + c8 * 8) =
                *reinterpret_cast<const uint4*>(g_Wl + gsrc);
        }
        __syncthreads();

        #pragma unroll
        for (int ks = 0; ks < 8; ++ks) {
            const int kb = ks * 16;
            uint32_t ah[2][4], al[2][4], bh[2][2], bl[2][2];
            #pragma unroll
            for (int mt = 0; mt < 2; ++mt) {
                uint32_t addr = smem_u32(sAhi + (wm + mt * 16 + a_row) * 136 + kb + a_kh);
                LDSM_X4(ah[mt][0], ah[mt][1], ah[mt][2], ah[mt][3], addr);
                addr = smem_u32(sAlo + (wm + mt * 16 + a_row) * 136 + kb + a_kh);
                LDSM_X4(al[mt][0], al[mt][1], al[mt][2], al[mt][3], addr);
            }
            {
                uint32_t addr = smem_u32(sBhi + (wn + b_row) * 136 + kb + b_kh);
                LDSM_X4(bh[0][0], bh[0][1], bh[1][0], bh[1][1], addr);
                addr = smem_u32(sBlo + (wn + b_row) * 136 + kb + b_kh);
                LDSM_X4(bl[0][0], bl[0][1], bl[1][0], bl[1][1], addr);
            }
            #pragma unroll
            for (int mt = 0; mt < 2; ++mt)
                #pragma unroll
                for (int nt = 0; nt < 2; ++nt) {
                    MMA_BF16(c[mt][nt], ah[mt], bh[nt]);
                    MMA_BF16(c[mt][nt], ah[mt], bl[nt]);
                    MMA_BF16(c[mt][nt], al[mt], bh[nt]);
                }
        }
        __syncthreads();
    }

    // epilogue
    const int g = lane >> 2, cl = (lane & 3) * 2;
    #pragma unroll
    for (int mt = 0; mt < 2; ++mt) {
        const int m = m0 + wm + mt * 16 + g;
        #pragma unroll
        for (int nt = 0; nt < 2; ++nt) {
            const int nl = wn + nt * 8 + cl;
            const int n  = n0 + nl;
            float f0 = c[mt][nt][0] + sbias[nl];
            float f1 = c[mt][nt][1] + sbias[nl + 1];
            float f2 = c[mt][nt][2] + sbias[nl];
            float f3 = c[mt][nt][3] + sbias[nl + 1];
            if (RELU) {
                f0 = fmaxf(f0, 0.f); f1 = fmaxf(f1, 0.f);
                f2 = fmaxf(f2, 0.f); f3 = fmaxf(f3, 0.f);
            }
            if (OUTMODE == 0) {
                *reinterpret_cast<float2*>(Cf + (size_t)m * D + n)       = make_float2(f0, f1);
                *reinterpret_cast<float2*>(Cf + (size_t)(m + 8) * D + n) = make_float2(f2, f3);
            } else if (OUTMODE == 1) {
                *reinterpret_cast<__half2*>(Ch + (size_t)m * D + n) =
                    __float22half2_rn(make_float2(f0, f1));
                *reinterpret_cast<__half2*>(Ch + (size_t)(m + 8) * D + n) =
                    __float22half2_rn(make_float2(f2, f3));
            } else {
                uint32_t h01, l01, h23, l23;
                split2(f0, f1, h01, l01);
                split2(f2, f3, h23, l23);
                *reinterpret_cast<uint32_t*>(Ohi + (size_t)m * D + n)       = h01;
                *reinterpret_cast<uint32_t*>(Olo + (size_t)m * D + n)       = l01;
                *reinterpret_cast<uint32_t*>(Ohi + (size_t)(m + 8) * D + n) = h23;
                *reinterpret_cast<uint32_t*>(Olo + (size_t)(m + 8) * D + n) = l23;
            }
        }
    }
}

// ---------------- x pre-split ------------------------------------------------
__global__ void xsplit_kernel(const float* __restrict__ x,
                              ushort_t* __restrict__ XH, ushort_t* __restrict__ XL) {
    int i = blockIdx.x * blockDim.x + threadIdx.x;   // 5000*256 = N*D/4 exactly
    float4 v = reinterpret_cast<const float4*>(x)[i];
    uint32_t h01, h23, l01, l23;
    split4(v, h01, h23, l01, l23);
    *reinterpret_cast<uint2*>(XH + (size_t)i * 4) = make_uint2(h01, h23);
    *reinterpret_cast<uint2*>(XL + (size_t)i * 4) = make_uint2(l01, l23);
}

// ---------------- residual + LayerNorm, one warp per row --------------------
__global__ void ln_kernel(const float* __restrict__ U, const float* __restrict__ X,
                          const float* __restrict__ gamma, const float* __restrict__ beta,
                          float* __restrict__ out)
{
    const int r    = blockIdx.x * 8 + (threadIdx.x >> 5);
    const int lane = threadIdx.x & 31;
    float4 u  = reinterpret_cast<const float4*>(U + (size_t)r * D)[lane];
    float4 xv = reinterpret_cast<const float4*>(X + (size_t)r * D)[lane];
    float4 h = make_float4(u.x + xv.x, u.y + xv.y, u.z + xv.z, u.w + xv.w);

    float s = h.x + h.y + h.z + h.w;
    #pragma unroll
    for (int o = 16; o; o >>= 1) s += __shfl_xor_sync(0xffffffffu, s, o);
    const float mu = s * (1.0f / 128.0f);

    float4 d = make_float4(h.x - mu, h.y - mu, h.z - mu, h.w - mu);
    float ss = d.x * d.x + d.y * d.y + d.z * d.z + d.w * d.w;
    #pragma unroll
    for (int o = 16; o; o >>= 1) ss += __shfl_xor_sync(0xffffffffu, ss, o);
    const float rstd = rsqrtf(ss * (1.0f / 128.0f) + 1e-5f);

    float4 gm = reinterpret_cast<const float4*>(gamma)[lane];
    float4 bt = reinterpret_cast<const float4*>(beta)[lane];
    float4 o4 = make_float4(d.x * rstd * gm.x + bt.x, d.y * rstd * gm.y + bt.y,
                            d.z * rstd * gm.z + bt.z, d.w * rstd * gm.w + bt.w);
    reinterpret_cast<float4*>(out + (size_t)r * D)[lane] = o4;
}

// ---------------- weight pre-split -------------------------------------------
__global__ void wsplit_kernel(const float* __restrict__ Wm1, const float* __restrict__ Wm2,
                              const float* __restrict__ Wu1, const float* __restrict__ Wu2)
{
    int i = blockIdx.x * blockDim.x + threadIdx.x;
    if (i >= 81920) return;
    float f;
    if      (i < 16384) f = Wm1[i];
    else if (i < 32768) f = Wm2[i - 16384];
    else if (i < 65536) f = Wu1[i - 32768];
    else                f = Wu2[i - 65536];
    uint32_t u = __float_as_uint(f);
    g_Wh[i] = (ushort_t)(u >> 16);
    float lo = f - __uint_as_float(u & 0xFFFF0000u);
    g_Wl[i] = __bfloat16_as_ushort(__float2bfloat16(lo));
}

// ---------------- edge dtype sniff -------------------------------------------
__global__ void detect_kernel(const int* __restrict__ e) {
    if (threadIdx.x == 0) {
        int any = 0;
        for (int i = 1; i < 256; i += 2) any |= e[i];
        g_is64 = (any == 0) ? 1 : 0;
    }
}

// ---------------- CSR build (scatter-mean without float atomics) ------------
__global__ void zero_cur_kernel(int* __restrict__ CUR) {
    int i = blockIdx.x * blockDim.x + threadIdx.x;
    if (i < N_NODES) CUR[i] = 0;
}
__global__ void count_kernel(const void* __restrict__ eidx, int* __restrict__ CUR) {
    int e = blockIdx.x * blockDim.x + threadIdx.x;     // 2500*256 = E exact
    int dst = g_is64 ? (int)reinterpret_cast<const long long*>(eidx)[N_EDGES + e]
                     : reinterpret_cast<const int*>(eidx)[N_EDGES + e];
    atomicAdd(&CUR[dst], 1);
}
// hierarchical scan: per-block inclusive scan -> local exclusive ROW + BSUM
__global__ void scanA_kernel(const int* __restrict__ CUR, int* __restrict__ ROW,
                             int* __restrict__ BSUM) {
    __shared__ int s[1024];
    const int t = threadIdx.x;
    const int i = blockIdx.x * 1024 + t;
    int v = (i < N_NODES) ? CUR[i] : 0;
    s[t] = v;
    __syncthreads();
    for (int off = 1; off < 1024; off <<= 1) {
        int tmp = (t >= off) ? s[t - off] : 0;
        __syncthreads();
        s[t] += tmp;
        __syncthreads();
    }
    if (i < N_NODES) ROW[i] = s[t] - v;   // local exclusive
    if (t == 1023) BSUM[blockIdx.x] = s[1023];
}
__global__ void scanB_kernel(int* __restrict__ BSUM, int* __restrict__ ROW) {
    if (threadIdx.x == 0) {
        int run = 0;
        for (int b = 0; b < 40; b++) { int cv = BSUM[b]; BSUM[b] = run; run += cv; }
        ROW[N_NODES] = N_EDGES;
    }
}
__global__ void scanC_kernel(int* __restrict__ ROW, const int* __restrict__ BSUM,
                             int* __restrict__ CUR) {
    const int i = blockIdx.x * 1024 + threadIdx.x;
    if (i < N_NODES) {
        int r = ROW[i] + BSUM[blockIdx.x];
        ROW[i] = r;
        CUR[i] = r;       // cursor for fill
    }
}
__global__ void fill_kernel(const void* __restrict__ eidx, int* __restrict__ CUR,
                            int* __restrict__ EIDX) {
    int e = blockIdx.x * blockDim.x + threadIdx.x;
    int src, dst;
    if (g_is64) {
        const long long* p = reinterpret_cast<const long long*>(eidx);
        src = (int)p[e]; dst = (int)p[N_EDGES + e];
    } else {
        const int* p = reinterpret_cast<const int*>(eidx);
        src = p[e]; dst = p[N_EDGES + e];
    }
    int pos = atomicAdd(&CUR[dst], 1);
    EIDX[pos] = src;
}
// one warp per node: sum fp16 Y[src] over incoming edges, divide by degree,
// store mean pre-split as bf16 hi/lo (consumed directly by the update GEMM).
__global__ void gather_kernel(const __half* __restrict__ Y, const int* __restrict__ ROW,
                              const int* __restrict__ EIDX,
                              ushort_t* __restrict__ AGH, ushort_t* __restrict__ AGL) {
    const int n    = blockIdx.x * 8 + (threadIdx.x >> 5);
    const int lane = threadIdx.x & 31;
    const int s = ROW[n], e = ROW[n + 1];
    float4 a0 = make_float4(0.f, 0.f, 0.f, 0.f);
    float4 a1 = make_float4(0.f, 0.f, 0.f, 0.f);
    float4 a2 = make_float4(0.f, 0.f, 0.f, 0.f);
    float4 a3 = make_float4(0.f, 0.f, 0.f, 0.f);
    for (int base = s; base < e; base += 32) {
        const int cnt = min(32, e - base);
        int idx = (base + lane < e) ? EIDX[base + lane] : 0;
        int j = 0;
        for (; j + 4 <= cnt; j += 4) {
            int s0 = __shfl_sync(0xffffffffu, idx, j);
            int s1 = __shfl_sync(0xffffffffu, idx, j + 1);
            int s2 = __shfl_sync(0xffffffffu, idx, j + 2);
            int s3 = __shfl_sync(0xffffffffu, idx, j + 3);
            uint2 r0 = *reinterpret_cast<const uint2*>(Y + (size_t)s0 * D + lane * 4);
            uint2 r1 = *reinterpret_cast<const uint2*>(Y + (size_t)s1 * D + lane * 4);
            uint2 r2 = *reinterpret_cast<const uint2*>(Y + (size_t)s2 * D + lane * 4);
            uint2 r3 = *reinterpret_cast<const uint2*>(Y + (size_t)s3 * D + lane * 4);
            float2 f;
            f = __half22float2(*(__half2*)&r0.x); a0.x += f.x; a0.y += f.y;
            f = __half22float2(*(__half2*)&r0.y); a0.z += f.x; a0.w += f.y;
            f = __half22float2(*(__half2*)&r1.x); a1.x += f.x; a1.y += f.y;
            f = __half22float2(*(__half2*)&r1.y); a1.z += f.x; a1.w += f.y;
            f = __half22float2(*(__half2*)&r2.x); a2.x += f.x; a2.y += f.y;
            f = __half22float2(*(__half2*)&r2.y); a2.z += f.x; a2.w += f.y;
            f = __half22float2(*(__half2*)&r3.x); a3.x += f.x; a3.y += f.y;
            f = __half22float2(*(__half2*)&r3.y); a3.z += f.x; a3.w += f.y;
        }
        for (; j < cnt; ++j) {
            int s0 = __shfl_sync(0xffffffffu, idx, j);
            uint2 r0 = *reinterpret_cast<const uint2*>(Y + (size_t)s0 * D + lane * 4);
            float2 f;
            f = __half22float2(*(__half2*)&r0.x); a0.x += f.x; a0.y += f.y;
            f = __half22float2(*(__half2*)&r0.y); a0.z += f.x; a0.w += f.y;
        }
    }
    float4 acc;
    acc.x = (a0.x + a1.x) + (a2.x + a3.x);
    acc.y = (a0.y + a1.y) + (a2.y + a3.y);
    acc.z = (a0.z + a1.z) + (a2.z + a3.z);
    acc.w = (a0.w + a1.w) + (a2.w + a3.w);
    const float sc = 1.0f / (float)max(e - s, 1);
    acc.x *= sc; acc.y *= sc; acc.z *= sc; acc.w *= sc;
    uint32_t h01, h23, l01, l23;
    split4(acc, h01, h23, l01, l23);
    *reinterpret_cast<uint2*>(AGH + (size_t)n * D + lane * 4) = make_uint2(h01, h23);
    *reinterpret_cast<uint2*>(AGL + (size_t)n * D + lane * 4) = make_uint2(l01, l23);
}

// ---------------- launch -----------------------------------------------------
extern "C" void kernel_launch(void* const* d_in, const int* in_sizes, int n_in,
                              void* d_out, int out_size)
{
    const float* x     = (const float*)d_in[0];
    const void*  eidx  =               d_in[1];
    const float* Wm1   = (const float*)d_in[2];
    const float* bm1   = (const float*)d_in[3];
    const float* Wm2   = (const float*)d_in[4];
    const float* bm2   = (const float*)d_in[5];
    const float* Wu1   = (const float*)d_in[6];
    const float* bu1   = (const float*)d_in[7];
    const float* Wu2   = (const float*)d_in[8];
    const float* bu2   = (const float*)d_in[9];
    const float* gamma = (const float*)d_in[10];
    const float* beta  = (const float*)d_in[11];
    float* out = (float*)d_out;

    void *pXH, *pXL, *pH1H, *pH1L, *pAGH, *pAGL, *pY, *pU2;
    void *pROW, *pCUR, *pEIDX, *pBSUM;
    cudaGetSymbolAddress(&pXH,   g_XH);
    cudaGetSymbolAddress(&pXL,   g_XL);
    cudaGetSymbolAddress(&pH1H,  g_H1H);
    cudaGetSymbolAddress(&pH1L,  g_H1L);
    cudaGetSymbolAddress(&pAGH,  g_AGH);
    cudaGetSymbolAddress(&pAGL,  g_AGL);
    cudaGetSymbolAddress(&pY,    g_Y);
    cudaGetSymbolAddress(&pU2,   g_U2);
    cudaGetSymbolAddress(&pROW,  g_ROW);
    cudaGetSymbolAddress(&pCUR,  g_CUR);
    cudaGetSymbolAddress(&pEIDX, g_EIDX);
    cudaGetSymbolAddress(&pBSUM, g_BSUM);

    // smem: 512 hdr + A hi/lo + B hi/lo, each 64x136 shorts
    const int SM64 = 512 + 4 * (64 * 136 * 2);   // 70144 -> 3 CTAs/SM
    cudaFuncSetAttribute(gemm64<128, true,  2>, cudaFuncAttributeMaxDynamicSharedMemorySize, SM64);
    cudaFuncSetAttribute(gemm64<128, false, 1>, cudaFuncAttributeMaxDynamicSharedMemorySize, SM64);
    cudaFuncSetAttribute(gemm64<256, true,  2>, cudaFuncAttributeMaxDynamicSharedMemorySize, SM64);
    cudaFuncSetAttribute(gemm64<128, false, 0>, cudaFuncAttributeMaxDynamicSharedMemorySize, SM64);

    const int GG = 1250;   // 625 m-tiles x 2 n-tiles
    const ushort_t* XH  = (const ushort_t*)pXH;
    const ushort_t* XL  = (const ushort_t*)pXL;
    const ushort_t* H1H = (const ushort_t*)pH1H;
    const ushort_t* H1L = (const ushort_t*)pH1L;
    const ushort_t* AGH = (const ushort_t*)pAGH;
    const ushort_t* AGL = (const ushort_t*)pAGL;

    detect_kernel  <<<1, 32>>>((const int*)eidx);
    wsplit_kernel  <<<320, 256>>>(Wm1, Wm2, Wu1, Wu2);
    xsplit_kernel  <<<5000, 256>>>(x, (ushort_t*)pXH, (ushort_t*)pXL);
    zero_cur_kernel<<<157, 256>>>((int*)pCUR);
    count_kernel   <<<2500, 256>>>(eidx, (int*)pCUR);
    scanA_kernel   <<<40, 1024>>>((const int*)pCUR, (int*)pROW, (int*)pBSUM);
    scanB_kernel   <<<1, 32>>>((int*)pBSUM, (int*)pROW);
    scanC_kernel   <<<40, 1024>>>((int*)pROW, (const int*)pBSUM, (int*)pCUR);
    fill_kernel    <<<2500, 256>>>(eidx, (int*)pCUR, (int*)pEIDX);

    // message MLP (per-node, algebraically identical to per-edge)
    gemm64<128, true,  2><<<GG, 256, SM64>>>(XH, XL, nullptr, nullptr, 0, bm1,
                                             nullptr, nullptr, (ushort_t*)pH1H, (ushort_t*)pH1L);
    gemm64<128, false, 1><<<GG, 256, SM64>>>(H1H, H1L, nullptr, nullptr, 16384, bm2,
                                             nullptr, (__half*)pY, nullptr, nullptr);
    // CSR gather-mean over fp16 Y, emits pre-split AGG
    gather_kernel<<<5000, 256>>>((const __half*)pY, (const int*)pROW,
                                 (const int*)pEIDX, (ushort_t*)pAGH, (ushort_t*)pAGL);
    // update MLP on concat([x, agg])
    gemm64<256, true,  2><<<GG, 256, SM64>>>(XH, XL, AGH, AGL, 32768, bu1,
                                             nullptr, nullptr, (ushort_t*)pH1H, (ushort_t*)pH1L);
    gemm64<128, false, 0><<<GG, 256, SM64>>>(H1H, H1L, nullptr, nullptr, 65536, bu2,
                                             (float*)pU2, nullptr, nullptr, nullptr);
    // residual + LayerNorm
    ln_kernel<<<5000, 256>>>((const float*)pU2, x, gamma, beta, out);
}

// round 15
// speedup vs baseline: 1.1355x; 1.1355x over previous
#include <cuda_runtime.h>
#include <cuda_bf16.h>
#include <cuda_fp16.h>
#include <cstdint>

#define N_NODES 40000
#define N_EDGES 640000
#define D 128

// ---------------- scratch (device globals: no allocations allowed) ----------
static __device__ float  g_H1 [N_NODES * D];  // msg hidden, then upd hidden (U1)
static __device__ float  g_U2 [N_NODES * D];  // pre-LN update output
static __device__ __half g_Y  [N_NODES * D];  // per-node message output (fp16)
static __device__ float  g_AGG[N_NODES * D];  // scatter-mean result
static __device__ int    g_ROW[N_NODES + 1];  // CSR row offsets (by dst)
static __device__ int    g_CUR[N_NODES];      // counts, then fill cursors
static __device__ int    g_EIDX[N_EDGES];     // src ids grouped by dst
static __device__ int    g_BSUM[64];          // block totals for scan
static __device__ int    g_is64;              // edge_index dtype flag
// pre-split weights (bf16 hi / lo), [n][k] row-major:
//   Wm1 @ 0 (16384), Wm2 @ 16384, Wu1 @ 32768 (32768), Wu2 @ 65536
static __device__ unsigned short g_Wh[81920];
static __device__ unsigned short g_Wl[81920];

// ---------------- helpers ----------------------------------------------------
__device__ __forceinline__ uint32_t smem_u32(const void* p) {
    return (uint32_t)__cvta_generic_to_shared(p);
}

// split 4 fp32 -> bf16 hi (truncate) pairs + bf16 lo (rn of residual) pairs
__device__ __forceinline__ void split4(float4 v, uint32_t& h01, uint32_t& h23,
                                       uint32_t& l01, uint32_t& l23) {
    uint32_t u0 = __float_as_uint(v.x), u1 = __float_as_uint(v.y);
    uint32_t u2 = __float_as_uint(v.z), u3 = __float_as_uint(v.w);
    asm("prmt.b32 %0, %1, %2, 0x7632;" : "=r"(h01) : "r"(u0), "r"(u1));
    asm("prmt.b32 %0, %1, %2, 0x7632;" : "=r"(h23) : "r"(u2), "r"(u3));
    float lo0 = v.x - __uint_as_float(u0 & 0xFFFF0000u);
    float lo1 = v.y - __uint_as_float(u1 & 0xFFFF0000u);
    float lo2 = v.z - __uint_as_float(u2 & 0xFFFF0000u);
    float lo3 = v.w - __uint_as_float(u3 & 0xFFFF0000u);
    asm("cvt.rn.bf16x2.f32 %0, %1, %2;" : "=r"(l01) : "f"(lo1), "f"(lo0));
    asm("cvt.rn.bf16x2.f32 %0, %1, %2;" : "=r"(l23) : "f"(lo3), "f"(lo2));
}

#define LDSM_X4(r0, r1, r2, r3, addr) \
    asm volatile("ldmatrix.sync.aligned.m8n8.x4.shared.b16 {%0,%1,%2,%3}, [%4];" \
        : "=r"(r0), "=r"(r1), "=r"(r2), "=r"(r3) : "r"(addr))

#define MMA_BF16(c, a, b) \
    asm volatile("mma.sync.aligned.m16n8k16.row.col.f32.bf16.bf16.f32 " \
        "{%0,%1,%2,%3}, {%4,%5,%6,%7}, {%8,%9}, {%0,%1,%2,%3};" \
        : "+f"((c)[0]), "+f"((c)[1]), "+f"((c)[2]), "+f"((c)[3]) \
        : "r"((a)[0]), "r"((a)[1]), "r"((a)[2]), "r"((a)[3]), \
          "r"((b)[0]), "r"((b)[1]))

// ---------------- N=64-tile GEMM: occupancy 3 CTAs/SM -----------------------
// C[:, n0:n0+64] = act(concat(A0,A1) @ W^T + bias)[:, n0:n0+64]
// Tile M=64 x N=64, K-chunk 128, 256 thr (8 warps, 2m x 4n, warp tile 32x16).
// A split to bf16 hi/lo in-kernel; W pre-split in g_Wh/g_Wl. 3-pass mma.
template <int KT, bool RELU, bool HOUT>
__global__ __launch_bounds__(256, 3)
void gemm64(const float* __restrict__ A0, const float* __restrict__ A1,
            int woff, const float* __restrict__ bias,
            float* __restrict__ Cf, __half* __restrict__ Ch)
{
    extern __shared__ char smc[];
    float* sbias = (float*)smc;                               // 64 floats
    unsigned short* sAhi = (unsigned short*)(smc + 512);      // [64][136]
    unsigned short* sAlo = sAhi + 64 * 136;
    unsigned short* sBhi = sAlo + 64 * 136;                   // [64][136]
    unsigned short* sBlo = sBhi + 64 * 136;

    const int tid  = threadIdx.x;
    const int lane = tid & 31;
    const int wid  = tid >> 5;
    const int wm   = (wid >> 2) * 32;        // 0 / 32
    const int wn   = (wid & 3) * 16;         // 0/16/32/48
    const int m0   = (blockIdx.x >> 1) * 64;
    const int n0   = (blockIdx.x & 1) * 64;

    if (tid < 64) sbias[tid] = bias[n0 + tid];

    float c[2][2][4];
    #pragma unroll
    for (int i = 0; i < 2; i++)
        #pragma unroll
        for (int j = 0; j < 2; j++)
            #pragma unroll
            for (int q = 0; q < 4; q++) c[i][j][q] = 0.0f;

    const int a_row = lane & 15, a_kh = (lane >> 4) * 8;
    const int b_row = (lane >> 4) * 8 + (lane & 7);
    const int b_kh  = ((lane >> 3) & 1) * 8;

    const int nchunks = KT / 128;
    for (int kc = 0; kc < nchunks; ++kc) {
        const float* Asrc = (kc == 0) ? A0 : A1;

        // A tile: 64x128 fp32 -> hi/lo bf16 (2048 float4, 8 iters)
        #pragma unroll
        for (int it = 0; it < 8; ++it) {
            int idx  = tid + it * 256;
            int row  = idx >> 5;
            int col4 = idx & 31;
            float4 v = *reinterpret_cast<const float4*>(
                Asrc + (size_t)(m0 + row) * D + col4 * 4);
            uint32_t h01, h23, l01, l23;
            split4(v, h01, h23, l01, l23);
            *reinterpret_cast<uint2*>(sAhi + row * 136 + col4 * 4) = make_uint2(h01, h23);
            *reinterpret_cast<uint2*>(sAlo + row * 136 + col4 * 4) = make_uint2(l01, l23);
        }
        // B tile: pre-split bf16 weights, rows n0..n0+63 (1024 uint4, 4 iters)
        #pragma unroll
        for (int it = 0; it < 4; ++it) {
            int idx = tid + it * 256;
            int row = idx >> 4;
            int c8  = idx & 15;
            size_t gsrc = (size_t)woff + (size_t)(n0 + row) * KT + kc * 128 + c8 * 8;
            *reinterpret_cast<uint4*>(sBhi + row * 136 + c8 * 8) =
                *reinterpret_cast<const uint4*>(g_Wh + gsrc);
            *reinterpret_cast<uint4*>(sBlo + row * 136 + c8 * 8) =
                *reinterpret_cast<const uint4*>(g_Wl + gsrc);
        }
        __syncthreads();

        #pragma unroll
        for (int ks = 0; ks < 8; ++ks) {
            const int kb = ks * 16;
            uint32_t ah[2][4], al[2][4], bh[2][2], bl[2][2];
            #pragma unroll
            for (int mt = 0; mt < 2; ++mt) {
                uint32_t addr = smem_u32(sAhi + (wm + mt * 16 + a_row) * 136 + kb + a_kh);
                LDSM_X4(ah[mt][0], ah[mt][1], ah[mt][2], ah[mt][3], addr);
                addr = smem_u32(sAlo + (wm + mt * 16 + a_row) * 136 + kb + a_kh);
                LDSM_X4(al[mt][0], al[mt][1], al[mt][2], al[mt][3], addr);
            }
            {
                uint32_t addr = smem_u32(sBhi + (wn + b_row) * 136 + kb + b_kh);
                LDSM_X4(bh[0][0], bh[0][1], bh[1][0], bh[1][1], addr);
                addr = smem_u32(sBlo + (wn + b_row) * 136 + kb + b_kh);
                LDSM_X4(bl[0][0], bl[0][1], bl[1][0], bl[1][1], addr);
            }
            #pragma unroll
            for (int mt = 0; mt < 2; ++mt)
                #pragma unroll
                for (int nt = 0; nt < 2; ++nt) {
                    MMA_BF16(c[mt][nt], ah[mt], bh[nt]);
                    MMA_BF16(c[mt][nt], ah[mt], bl[nt]);
                    MMA_BF16(c[mt][nt], al[mt], bh[nt]);
                }
        }
        __syncthreads();
    }

    // epilogue
    const int g = lane >> 2, cl = (lane & 3) * 2;
    #pragma unroll
    for (int mt = 0; mt < 2; ++mt) {
        const int m = m0 + wm + mt * 16 + g;
        #pragma unroll
        for (int nt = 0; nt < 2; ++nt) {
            const int nl = wn + nt * 8 + cl;
            const int n  = n0 + nl;
            float f0 = c[mt][nt][0] + sbias[nl];
            float f1 = c[mt][nt][1] + sbias[nl + 1];
            float f2 = c[mt][nt][2] + sbias[nl];
            float f3 = c[mt][nt][3] + sbias[nl + 1];
            if (RELU) {
                f0 = fmaxf(f0, 0.f); f1 = fmaxf(f1, 0.f);
                f2 = fmaxf(f2, 0.f); f3 = fmaxf(f3, 0.f);
            }
            if (HOUT) {
                *reinterpret_cast<__half2*>(Ch + (size_t)m * D + n) =
                    __float22half2_rn(make_float2(f0, f1));
                *reinterpret_cast<__half2*>(Ch + (size_t)(m + 8) * D + n) =
                    __float22half2_rn(make_float2(f2, f3));
            } else {
                *reinterpret_cast<float2*>(Cf + (size_t)m * D + n)       = make_float2(f0, f1);
                *reinterpret_cast<float2*>(Cf + (size_t)(m + 8) * D + n) = make_float2(f2, f3);
            }
        }
    }
}

// ---------------- residual + LayerNorm, one warp per row --------------------
__global__ void ln_kernel(const float* __restrict__ U, const float* __restrict__ X,
                          const float* __restrict__ gamma, const float* __restrict__ beta,
                          float* __restrict__ out)
{
    const int r    = blockIdx.x * 8 + (threadIdx.x >> 5);
    const int lane = threadIdx.x & 31;
    float4 u  = reinterpret_cast<const float4*>(U + (size_t)r * D)[lane];
    float4 xv = reinterpret_cast<const float4*>(X + (size_t)r * D)[lane];
    float4 h = make_float4(u.x + xv.x, u.y + xv.y, u.z + xv.z, u.w + xv.w);

    float s = h.x + h.y + h.z + h.w;
    #pragma unroll
    for (int o = 16; o; o >>= 1) s += __shfl_xor_sync(0xffffffffu, s, o);
    const float mu = s * (1.0f / 128.0f);

    float4 d = make_float4(h.x - mu, h.y - mu, h.z - mu, h.w - mu);
    float ss = d.x * d.x + d.y * d.y + d.z * d.z + d.w * d.w;
    #pragma unroll
    for (int o = 16; o; o >>= 1) ss += __shfl_xor_sync(0xffffffffu, ss, o);
    const float rstd = rsqrtf(ss * (1.0f / 128.0f) + 1e-5f);

    float4 gm = reinterpret_cast<const float4*>(gamma)[lane];
    float4 bt = reinterpret_cast<const float4*>(beta)[lane];
    float4 o4 = make_float4(d.x * rstd * gm.x + bt.x, d.y * rstd * gm.y + bt.y,
                            d.z * rstd * gm.z + bt.z, d.w * rstd * gm.w + bt.w);
    reinterpret_cast<float4*>(out + (size_t)r * D)[lane] = o4;
}

// ---------------- weight pre-split + CUR zero + edge dtype sniff ------------
// 320 blocks x 256 = 81920 threads: covers 81920 weights and 40000 CUR slots.
// Warp 0 of block 0 additionally sniffs the edge dtype (parallel __any_sync).
__global__ void prep_kernel(const float* __restrict__ Wm1, const float* __restrict__ Wm2,
                            const float* __restrict__ Wu1, const float* __restrict__ Wu2,
                            const int* __restrict__ e, int* __restrict__ CUR)
{
    int i = blockIdx.x * blockDim.x + threadIdx.x;
    if (i < N_NODES) CUR[i] = 0;
    if (blockIdx.x == 0 && threadIdx.x < 32) {
        // int64 values < 2^31 viewed as int32 have every odd slot == 0
        int any = 0;
        #pragma unroll
        for (int j = 0; j < 4; j++) any |= e[1 + 2 * (threadIdx.x * 4 + j)];
        int found = __any_sync(0xffffffffu, any != 0);
        if (threadIdx.x == 0) g_is64 = found ? 0 : 1;
    }
    if (i < 81920) {
        float f;
        if      (i < 16384) f = Wm1[i];
        else if (i < 32768) f = Wm2[i - 16384];
        else if (i < 65536) f = Wu1[i - 32768];
        else                f = Wu2[i - 65536];
        uint32_t u = __float_as_uint(f);
        g_Wh[i] = (unsigned short)(u >> 16);
        float lo = f - __uint_as_float(u & 0xFFFF0000u);
        g_Wl[i] = __bfloat16_as_ushort(__float2bfloat16(lo));
    }
}

// ---------------- CSR build (scatter-mean without float atomics) ------------
__global__ void count_kernel(const void* __restrict__ eidx, int* __restrict__ CUR) {
    int e = blockIdx.x * blockDim.x + threadIdx.x;     // 2500*256 = E exact
    int dst = g_is64 ? (int)reinterpret_cast<const long long*>(eidx)[N_EDGES + e]
                     : reinterpret_cast<const int*>(eidx)[N_EDGES + e];
    atomicAdd(&CUR[dst], 1);
}
// per-block inclusive scan -> local exclusive ROW + block totals BSUM
__global__ void scanA_kernel(const int* __restrict__ CUR, int* __restrict__ ROW,
                             int* __restrict__ BSUM) {
    __shared__ int s[1024];
    const int t = threadIdx.x;
    const int i = blockIdx.x * 1024 + t;
    int v = (i < N_NODES) ? CUR[i] : 0;
    s[t] = v;
    __syncthreads();
    for (int off = 1; off < 1024; off <<= 1) {
        int tmp = (t >= off) ? s[t - off] : 0;
        __syncthreads();
        s[t] += tmp;
        __syncthreads();
    }
    if (i < N_NODES) ROW[i] = s[t] - v;   // local exclusive
    if (t == 1023) BSUM[blockIdx.x] = s[1023];
}
// apply block-offset (each block prefix-sums BSUM itself; no separate pass)
__global__ void scanC_kernel(int* __restrict__ ROW, const int* __restrict__ BSUM,
                             int* __restrict__ CUR) {
    __shared__ int soff;
    if (threadIdx.x == 0) {
        int run = 0;
        for (int b = 0; b < (int)blockIdx.x; b++) run += BSUM[b];
        soff = run;
        if (blockIdx.x == 0) ROW[N_NODES] = N_EDGES;
    }
    __syncthreads();
    const int i = blockIdx.x * 1024 + threadIdx.x;
    if (i < N_NODES) {
        int r = ROW[i] + soff;
        ROW[i] = r;
        CUR[i] = r;       // cursor for fill
    }
}
__global__ void fill_kernel(const void* __restrict__ eidx, int* __restrict__ CUR,
                            int* __restrict__ EIDX) {
    int e = blockIdx.x * blockDim.x + threadIdx.x;
    int src, dst;
    if (g_is64) {
        const long long* p = reinterpret_cast<const long long*>(eidx);
        src = (int)p[e]; dst = (int)p[N_EDGES + e];
    } else {
        const int* p = reinterpret_cast<const int*>(eidx);
        src = p[e]; dst = p[N_EDGES + e];
    }
    int pos = atomicAdd(&CUR[dst], 1);
    EIDX[pos] = src;
}
// one warp per node: sum fp16 Y[src] over incoming edges, divide by degree.
__global__ void gather_kernel(const __half* __restrict__ Y, const int* __restrict__ ROW,
                              const int* __restrict__ EIDX, float* __restrict__ AGG) {
    const int n    = blockIdx.x * 8 + (threadIdx.x >> 5);
    const int lane = threadIdx.x & 31;
    const int s = ROW[n], e = ROW[n + 1];
    float4 a0 = make_float4(0.f, 0.f, 0.f, 0.f);
    float4 a1 = make_float4(0.f, 0.f, 0.f, 0.f);
    float4 a2 = make_float4(0.f, 0.f, 0.f, 0.f);
    float4 a3 = make_float4(0.f, 0.f, 0.f, 0.f);
    for (int base = s; base < e; base += 32) {
        const int cnt = min(32, e - base);
        int idx = (base + lane < e) ? EIDX[base + lane] : 0;
        int j = 0;
        for (; j + 4 <= cnt; j += 4) {
            int s0 = __shfl_sync(0xffffffffu, idx, j);
            int s1 = __shfl_sync(0xffffffffu, idx, j + 1);
            int s2 = __shfl_sync(0xffffffffu, idx, j + 2);
            int s3 = __shfl_sync(0xffffffffu, idx, j + 3);
            uint2 r0 = *reinterpret_cast<const uint2*>(Y + (size_t)s0 * D + lane * 4);
            uint2 r1 = *reinterpret_cast<const uint2*>(Y + (size_t)s1 * D + lane * 4);
            uint2 r2 = *reinterpret_cast<const uint2*>(Y + (size_t)s2 * D + lane * 4);
            uint2 r3 = *reinterpret_cast<const uint2*>(Y + (size_t)s3 * D + lane * 4);
            float2 f;
            f = __half22float2(*(__half2*)&r0.x); a0.x += f.x; a0.y += f.y;
            f = __half22float2(*(__half2*)&r0.y); a0.z += f.x; a0.w += f.y;
            f = __half22float2(*(__half2*)&r1.x); a1.x += f.x; a1.y += f.y;
            f = __half22float2(*(__half2*)&r1.y); a1.z += f.x; a1.w += f.y;
            f = __half22float2(*(__half2*)&r2.x); a2.x += f.x; a2.y += f.y;
            f = __half22float2(*(__half2*)&r2.y); a2.z += f.x; a2.w += f.y;
            f = __half22float2(*(__half2*)&r3.x); a3.x += f.x; a3.y += f.y;
            f = __half22float2(*(__half2*)&r3.y); a3.z += f.x; a3.w += f.y;
        }
        for (; j < cnt; ++j) {
            int s0 = __shfl_sync(0xffffffffu, idx, j);
            uint2 r0 = *reinterpret_cast<const uint2*>(Y + (size_t)s0 * D + lane * 4);
            float2 f;
            f = __half22float2(*(__half2*)&r0.x); a0.x += f.x; a0.y += f.y;
            f = __half22float2(*(__half2*)&r0.y); a0.z += f.x; a0.w += f.y;
        }
    }
    float4 acc;
    acc.x = (a0.x + a1.x) + (a2.x + a3.x);
    acc.y = (a0.y + a1.y) + (a2.y + a3.y);
    acc.z = (a0.z + a1.z) + (a2.z + a3.z);
    acc.w = (a0.w + a1.w) + (a2.w + a3.w);
    const float sc = 1.0f / (float)max(e - s, 1);
    acc.x *= sc; acc.y *= sc; acc.z *= sc; acc.w *= sc;
    reinterpret_cast<float4*>(AGG + (size_t)n * D)[lane] = acc;
}

// ---------------- launch -----------------------------------------------------
extern "C" void kernel_launch(void* const* d_in, const int* in_sizes, int n_in,
                              void* d_out, int out_size)
{
    const float* x     = (const float*)d_in[0];
    const void*  eidx  =               d_in[1];
    const float* Wm1   = (const float*)d_in[2];
    const float* bm1   = (const float*)d_in[3];
    const float* Wm2   = (const float*)d_in[4];
    const float* bm2   = (const float*)d_in[5];
    const float* Wu1   = (const float*)d_in[6];
    const float* bu1   = (const float*)d_in[7];
    const float* Wu2   = (const float*)d_in[8];
    const float* bu2   = (const float*)d_in[9];
    const float* gamma = (const float*)d_in[10];
    const float* beta  = (const float*)d_in[11];
    float* out = (float*)d_out;

    void *pH1, *pU2, *pY, *pAGG, *pROW, *pCUR, *pEIDX, *pBSUM;
    cudaGetSymbolAddress(&pH1,   g_H1);
    cudaGetSymbolAddress(&pU2,   g_U2);
    cudaGetSymbolAddress(&pY,    g_Y);
    cudaGetSymbolAddress(&pAGG,  g_AGG);
    cudaGetSymbolAddress(&pROW,  g_ROW);
    cudaGetSymbolAddress(&pCUR,  g_CUR);
    cudaGetSymbolAddress(&pEIDX, g_EIDX);
    cudaGetSymbolAddress(&pBSUM, g_BSUM);

    // smem: 512 hdr + A hi/lo + B hi/lo, each 64x136 shorts
    const int SM64 = 512 + 4 * (64 * 136 * 2);   // 70144 -> 3 CTAs/SM
    cudaFuncSetAttribute(gemm64<128, true,  false>, cudaFuncAttributeMaxDynamicSharedMemorySize, SM64);
    cudaFuncSetAttribute(gemm64<128, false, true >, cudaFuncAttributeMaxDynamicSharedMemorySize, SM64);
    cudaFuncSetAttribute(gemm64<256, true,  false>, cudaFuncAttributeMaxDynamicSharedMemorySize, SM64);
    cudaFuncSetAttribute(gemm64<128, false, false>, cudaFuncAttributeMaxDynamicSharedMemorySize, SM64);

    const int GG = 1250;   // 625 m-tiles x 2 n-tiles

    // weights split + CUR zero + dtype sniff, one launch
    prep_kernel <<<320, 256>>>(Wm1, Wm2, Wu1, Wu2, (const int*)eidx, (int*)pCUR);
    count_kernel<<<2500, 256>>>(eidx, (int*)pCUR);
    scanA_kernel<<<40, 1024>>>((const int*)pCUR, (int*)pROW, (int*)pBSUM);
    scanC_kernel<<<40, 1024>>>((int*)pROW, (const int*)pBSUM, (int*)pCUR);
    fill_kernel <<<2500, 256>>>(eidx, (int*)pCUR, (int*)pEIDX);

    // message MLP (per-node, algebraically identical to per-edge)
    gemm64<128, true,  false><<<GG, 256, SM64>>>(x, nullptr, 0,     bm1, (float*)pH1, nullptr);
    gemm64<128, false, true ><<<GG, 256, SM64>>>((const float*)pH1, nullptr, 16384, bm2, nullptr, (__half*)pY);
    // CSR gather-mean over fp16 Y
    gather_kernel<<<5000, 256>>>((const __half*)pY, (const int*)pROW,
                                 (const int*)pEIDX, (float*)pAGG);
    // update MLP on concat([x, agg])
    gemm64<256, true,  false><<<GG, 256, SM64>>>(x, (const float*)pAGG, 32768, bu1, (float*)pH1, nullptr);
    gemm64<128, false, false><<<GG, 256, SM64>>>((const float*)pH1, nullptr, 65536, bu2, (float*)pU2, nullptr);
    // residual + LayerNorm
    ln_kernel<<<5000, 256>>>((const float*)pU2, x, gamma, beta, out);
}

// round 16
// speedup vs baseline: 1.5146x; 1.3338x over previous
#include <cuda_runtime.h>
#include <cuda_bf16.h>
#include <cuda_fp16.h>
#include <cstdint>

#define N_NODES 40000
#define N_EDGES 640000
#define D 128

// ---------------- scratch (device globals: no allocations allowed) ----------
static __device__ __half g_H1 [N_NODES * D];  // msg hidden, then upd hidden (fp16)
static __device__ float  g_U2 [N_NODES * D];  // pre-LN update output
static __device__ __half g_Y  [N_NODES * D];  // per-node message output (fp16)
static __device__ __half g_AGG[N_NODES * D];  // scatter-mean result (fp16)
static __device__ int    g_ROW[N_NODES + 1];  // CSR row offsets (by dst)
static __device__ int    g_CUR[N_NODES];      // counts, then fill cursors
static __device__ int    g_EIDX[N_EDGES];     // src ids grouped by dst
static __device__ int    g_BSUM[64];          // block totals for scan
static __device__ int    g_is64;              // edge_index dtype flag
// pre-converted fp16 weights, [n][k] row-major:
//   Wm1 @ 0 (16384), Wm2 @ 16384, Wu1 @ 32768 (32768), Wu2 @ 65536
static __device__ __half g_Wf[81920];

// ---------------- helpers ----------------------------------------------------
__device__ __forceinline__ uint32_t smem_u32(const void* p) {
    return (uint32_t)__cvta_generic_to_shared(p);
}

#define LDSM_X4(r0, r1, r2, r3, addr) \
    asm volatile("ldmatrix.sync.aligned.m8n8.x4.shared.b16 {%0,%1,%2,%3}, [%4];" \
        : "=r"(r0), "=r"(r1), "=r"(r2), "=r"(r3) : "r"(addr))

#define MMA_F16(c, a, b) \
    asm volatile("mma.sync.aligned.m16n8k16.row.col.f32.f16.f16.f32 " \
        "{%0,%1,%2,%3}, {%4,%5,%6,%7}, {%8,%9}, {%0,%1,%2,%3};" \
        : "+f"((c)[0]), "+f"((c)[1]), "+f"((c)[2]), "+f"((c)[3]) \
        : "r"((a)[0]), "r"((a)[1]), "r"((a)[2]), "r"((a)[3]), \
          "r"((b)[0]), "r"((b)[1]))

// ---------------- N=64-tile fp16 GEMM: single-pass, 4 CTAs/SM ---------------
// C[:, n0:n0+64] = act(concat(A0,A1) @ W^T + bias)[:, n0:n0+64]
// Tile M=64 x N=64, K-chunk 128, 256 thr (8 warps, 2m x 4n, warp tile 32x16).
// A converted (or copied if already fp16) into smem; W pre-fp16 in g_Wf.
// fp16 x fp16 products are exact in the fp32 accumulator -> only input
// rounding (~2^-12 RMS) contributes; measured pipeline tolerance >> that.
// A0H/A1H: whether chunk-0 / chunk-1 A source is already fp16.
template <int KT, bool RELU, bool HOUT, bool A0H, bool A1H>
__global__ __launch_bounds__(256, 4)
void gemm64f(const void* __restrict__ A0, const void* __restrict__ A1,
             int woff, const float* __restrict__ bias,
             float* __restrict__ Cf, __half* __restrict__ Ch)
{
    extern __shared__ char smc[];
    float* sbias = (float*)smc;                       // 64 floats
    __half* sA = (__half*)(smc + 512);                // [64][136]
    __half* sB = sA + 64 * 136;                       // [64][136]

    const int tid  = threadIdx.x;
    const int lane = tid & 31;
    const int wid  = tid >> 5;
    const int wm   = (wid >> 2) * 32;        // 0 / 32
    const int wn   = (wid & 3) * 16;         // 0/16/32/48
    const int m0   = (blockIdx.x >> 1) * 64;
    const int n0   = (blockIdx.x & 1) * 64;

    if (tid < 64) sbias[tid] = bias[n0 + tid];

    float c[2][2][4];
    #pragma unroll
    for (int i = 0; i < 2; i++)
        #pragma unroll
        for (int j = 0; j < 2; j++)
            #pragma unroll
            for (int q = 0; q < 4; q++) c[i][j][q] = 0.0f;

    const int a_row = lane & 15, a_kh = (lane >> 4) * 8;
    const int b_row = (lane >> 4) * 8 + (lane & 7);
    const int b_kh  = ((lane >> 3) & 1) * 8;

    const int nchunks = KT / 128;
    #pragma unroll
    for (int kc = 0; kc < nchunks; ++kc) {
        const bool ah16 = (kc == 0) ? A0H : A1H;
        const void* Asrc = (kc == 0) ? A0 : A1;

        if (!ah16) {
            // fp32 -> fp16 convert: 2048 float4 over 8 iters
            const float* Af = (const float*)Asrc;
            #pragma unroll
            for (int it = 0; it < 8; ++it) {
                int idx  = tid + it * 256;
                int row  = idx >> 5;
                int col4 = idx & 31;
                float4 v = *reinterpret_cast<const float4*>(
                    Af + (size_t)(m0 + row) * D + col4 * 4);
                __half2 h01 = __float22half2_rn(make_float2(v.x, v.y));
                __half2 h23 = __float22half2_rn(make_float2(v.z, v.w));
                *reinterpret_cast<uint2*>(sA + row * 136 + col4 * 4) =
                    make_uint2(*(uint32_t*)&h01, *(uint32_t*)&h23);
            }
        } else {
            // already fp16: pure uint4 copy, 1024 over 4 iters
            const __half* Ah = (const __half*)Asrc;
            #pragma unroll
            for (int it = 0; it < 4; ++it) {
                int idx = tid + it * 256;
                int row = idx >> 4;
                int c8  = idx & 15;
                *reinterpret_cast<uint4*>(sA + row * 136 + c8 * 8) =
                    *reinterpret_cast<const uint4*>(Ah + (size_t)(m0 + row) * D + c8 * 8);
            }
        }
        // B tile: fp16 weights rows n0..n0+63
        #pragma unroll
        for (int it = 0; it < 4; ++it) {
            int idx = tid + it * 256;
            int row = idx >> 4;
            int c8  = idx & 15;
            size_t gsrc = (size_t)woff + (size_t)(n0 + row) * KT + kc * 128 + c8 * 8;
            *reinterpret_cast<uint4*>(sB + row * 136 + c8 * 8) =
                *reinterpret_cast<const uint4*>(g_Wf + gsrc);
        }
        __syncthreads();

        #pragma unroll
        for (int ks = 0; ks < 8; ++ks) {
            const int kb = ks * 16;
            uint32_t ah[2][4], bh[2][2];
            #pragma unroll
            for (int mt = 0; mt < 2; ++mt) {
                uint32_t addr = smem_u32(sA + (wm + mt * 16 + a_row) * 136 + kb + a_kh);
                LDSM_X4(ah[mt][0], ah[mt][1], ah[mt][2], ah[mt][3], addr);
            }
            {
                uint32_t addr = smem_u32(sB + (wn + b_row) * 136 + kb + b_kh);
                LDSM_X4(bh[0][0], bh[0][1], bh[1][0], bh[1][1], addr);
            }
            #pragma unroll
            for (int mt = 0; mt < 2; ++mt)
                #pragma unroll
                for (int nt = 0; nt < 2; ++nt)
                    MMA_F16(c[mt][nt], ah[mt], bh[nt]);
        }
        __syncthreads();
    }

    // epilogue
    const int g = lane >> 2, cl = (lane & 3) * 2;
    #pragma unroll
    for (int mt = 0; mt < 2; ++mt) {
        const int m = m0 + wm + mt * 16 + g;
        #pragma unroll
        for (int nt = 0; nt < 2; ++nt) {
            const int nl = wn + nt * 8 + cl;
            const int n  = n0 + nl;
            float f0 = c[mt][nt][0] + sbias[nl];
            float f1 = c[mt][nt][1] + sbias[nl + 1];
            float f2 = c[mt][nt][2] + sbias[nl];
            float f3 = c[mt][nt][3] + sbias[nl + 1];
            if (RELU) {
                f0 = fmaxf(f0, 0.f); f1 = fmaxf(f1, 0.f);
                f2 = fmaxf(f2, 0.f); f3 = fmaxf(f3, 0.f);
            }
            if (HOUT) {
                *reinterpret_cast<__half2*>(Ch + (size_t)m * D + n) =
                    __float22half2_rn(make_float2(f0, f1));
                *reinterpret_cast<__half2*>(Ch + (size_t)(m + 8) * D + n) =
                    __float22half2_rn(make_float2(f2, f3));
            } else {
                *reinterpret_cast<float2*>(Cf + (size_t)m * D + n)       = make_float2(f0, f1);
                *reinterpret_cast<float2*>(Cf + (size_t)(m + 8) * D + n) = make_float2(f2, f3);
            }
        }
    }
}

// ---------------- residual + LayerNorm, one warp per row --------------------
__global__ void ln_kernel(const float* __restrict__ U, const float* __restrict__ X,
                          const float* __restrict__ gamma, const float* __restrict__ beta,
                          float* __restrict__ out)
{
    const int r    = blockIdx.x * 8 + (threadIdx.x >> 5);
    const int lane = threadIdx.x & 31;
    float4 u  = reinterpret_cast<const float4*>(U + (size_t)r * D)[lane];
    float4 xv = reinterpret_cast<const float4*>(X + (size_t)r * D)[lane];
    float4 h = make_float4(u.x + xv.x, u.y + xv.y, u.z + xv.z, u.w + xv.w);

    float s = h.x + h.y + h.z + h.w;
    #pragma unroll
    for (int o = 16; o; o >>= 1) s += __shfl_xor_sync(0xffffffffu, s, o);
    const float mu = s * (1.0f / 128.0f);

    float4 d = make_float4(h.x - mu, h.y - mu, h.z - mu, h.w - mu);
    float ss = d.x * d.x + d.y * d.y + d.z * d.z + d.w * d.w;
    #pragma unroll
    for (int o = 16; o; o >>= 1) ss += __shfl_xor_sync(0xffffffffu, ss, o);
    const float rstd = rsqrtf(ss * (1.0f / 128.0f) + 1e-5f);

    float4 gm = reinterpret_cast<const float4*>(gamma)[lane];
    float4 bt = reinterpret_cast<const float4*>(beta)[lane];
    float4 o4 = make_float4(d.x * rstd * gm.x + bt.x, d.y * rstd * gm.y + bt.y,
                            d.z * rstd * gm.z + bt.z, d.w * rstd * gm.w + bt.w);
    reinterpret_cast<float4*>(out + (size_t)r * D)[lane] = o4;
}

// ---------------- weight fp16 convert + CUR zero + edge dtype sniff ---------
__global__ void prep_kernel(const float* __restrict__ Wm1, const float* __restrict__ Wm2,
                            const float* __restrict__ Wu1, const float* __restrict__ Wu2,
                            const int* __restrict__ e, int* __restrict__ CUR)
{
    int i = blockIdx.x * blockDim.x + threadIdx.x;
    if (i < N_NODES) CUR[i] = 0;
    if (blockIdx.x == 0 && threadIdx.x < 32) {
        // int64 values < 2^31 viewed as int32 have every odd slot == 0
        int any = 0;
        #pragma unroll
        for (int j = 0; j < 4; j++) any |= e[1 + 2 * (threadIdx.x * 4 + j)];
        int found = __any_sync(0xffffffffu, any != 0);
        if (threadIdx.x == 0) g_is64 = found ? 0 : 1;
    }
    if (i < 81920) {
        float f;
        if      (i < 16384) f = Wm1[i];
        else if (i < 32768) f = Wm2[i - 16384];
        else if (i < 65536) f = Wu1[i - 32768];
        else                f = Wu2[i - 65536];
        g_Wf[i] = __float2half_rn(f);
    }
}

// ---------------- CSR build (scatter-mean without float atomics) ------------
__global__ void count_kernel(const void* __restrict__ eidx, int* __restrict__ CUR) {
    int e = blockIdx.x * blockDim.x + threadIdx.x;     // 2500*256 = E exact
    int dst = g_is64 ? (int)reinterpret_cast<const long long*>(eidx)[N_EDGES + e]
                     : reinterpret_cast<const int*>(eidx)[N_EDGES + e];
    atomicAdd(&CUR[dst], 1);
}
// per-block inclusive scan -> local exclusive ROW + block totals BSUM
__global__ void scanA_kernel(const int* __restrict__ CUR, int* __restrict__ ROW,
                             int* __restrict__ BSUM) {
    __shared__ int s[1024];
    const int t = threadIdx.x;
    const int i = blockIdx.x * 1024 + t;
    int v = (i < N_NODES) ? CUR[i] : 0;
    s[t] = v;
    __syncthreads();
    for (int off = 1; off < 1024; off <<= 1) {
        int tmp = (t >= off) ? s[t - off] : 0;
        __syncthreads();
        s[t] += tmp;
        __syncthreads();
    }
    if (i < N_NODES) ROW[i] = s[t] - v;   // local exclusive
    if (t == 1023) BSUM[blockIdx.x] = s[1023];
}
// apply block-offset; BSUM staged through shared (no serial global loads)
__global__ void scanC_kernel(int* __restrict__ ROW, const int* __restrict__ BSUM,
                             int* __restrict__ CUR) {
    __shared__ int sb[40];
    __shared__ int soff;
    if (threadIdx.x < 40) sb[threadIdx.x] = BSUM[threadIdx.x];
    __syncthreads();
    if (threadIdx.x == 0) {
        int run = 0;
        for (int b = 0; b < (int)blockIdx.x; b++) run += sb[b];
        soff = run;
        if (blockIdx.x == 0) ROW[N_NODES] = N_EDGES;
    }
    __syncthreads();
    const int i = blockIdx.x * 1024 + threadIdx.x;
    if (i < N_NODES) {
        int r = ROW[i] + soff;
        ROW[i] = r;
        CUR[i] = r;       // cursor for fill
    }
}
__global__ void fill_kernel(const void* __restrict__ eidx, int* __restrict__ CUR,
                            int* __restrict__ EIDX) {
    int e = blockIdx.x * blockDim.x + threadIdx.x;
    int src, dst;
    if (g_is64) {
        const long long* p = reinterpret_cast<const long long*>(eidx);
        src = (int)p[e]; dst = (int)p[N_EDGES + e];
    } else {
        const int* p = reinterpret_cast<const int*>(eidx);
        src = p[e]; dst = p[N_EDGES + e];
    }
    int pos = atomicAdd(&CUR[dst], 1);
    EIDX[pos] = src;
}
// one warp per node: sum fp16 Y[src] over incoming edges, divide by degree,
// store mean as fp16 (consumed directly by the fp16 update GEMM).
__global__ void gather_kernel(const __half* __restrict__ Y, const int* __restrict__ ROW,
                              const int* __restrict__ EIDX, __half* __restrict__ AGG) {
    const int n    = blockIdx.x * 8 + (threadIdx.x >> 5);
    const int lane = threadIdx.x & 31;
    const int s = ROW[n], e = ROW[n + 1];
    float4 a0 = make_float4(0.f, 0.f, 0.f, 0.f);
    float4 a1 = make_float4(0.f, 0.f, 0.f, 0.f);
    float4 a2 = make_float4(0.f, 0.f, 0.f, 0.f);
    float4 a3 = make_float4(0.f, 0.f, 0.f, 0.f);
    for (int base = s; base < e; base += 32) {
        const int cnt = min(32, e - base);
        int idx = (base + lane < e) ? EIDX[base + lane] : 0;
        int j = 0;
        for (; j + 4 <= cnt; j += 4) {
            int s0 = __shfl_sync(0xffffffffu, idx, j);
            int s1 = __shfl_sync(0xffffffffu, idx, j + 1);
            int s2 = __shfl_sync(0xffffffffu, idx, j + 2);
            int s3 = __shfl_sync(0xffffffffu, idx, j + 3);
            uint2 r0 = *reinterpret_cast<const uint2*>(Y + (size_t)s0 * D + lane * 4);
            uint2 r1 = *reinterpret_cast<const uint2*>(Y + (size_t)s1 * D + lane * 4);
            uint2 r2 = *reinterpret_cast<const uint2*>(Y + (size_t)s2 * D + lane * 4);
            uint2 r3 = *reinterpret_cast<const uint2*>(Y + (size_t)s3 * D + lane * 4);
            float2 f;
            f = __half22float2(*(__half2*)&r0.x); a0.x += f.x; a0.y += f.y;
            f = __half22float2(*(__half2*)&r0.y); a0.z += f.x; a0.w += f.y;
            f = __half22float2(*(__half2*)&r1.x); a1.x += f.x; a1.y += f.y;
            f = __half22float2(*(__half2*)&r1.y); a1.z += f.x; a1.w += f.y;
            f = __half22float2(*(__half2*)&r2.x); a2.x += f.x; a2.y += f.y;
            f = __half22float2(*(__half2*)&r2.y); a2.z += f.x; a2.w += f.y;
            f = __half22float2(*(__half2*)&r3.x); a3.x += f.x; a3.y += f.y;
            f = __half22float2(*(__half2*)&r3.y); a3.z += f.x; a3.w += f.y;
        }
        for (; j < cnt; ++j) {
            int s0 = __shfl_sync(0xffffffffu, idx, j);
            uint2 r0 = *reinterpret_cast<const uint2*>(Y + (size_t)s0 * D + lane * 4);
            float2 f;
            f = __half22float2(*(__half2*)&r0.x); a0.x += f.x; a0.y += f.y;
            f = __half22float2(*(__half2*)&r0.y); a0.z += f.x; a0.w += f.y;
        }
    }
    float4 acc;
    acc.x = (a0.x + a1.x) + (a2.x + a3.x);
    acc.y = (a0.y + a1.y) + (a2.y + a3.y);
    acc.z = (a0.z + a1.z) + (a2.z + a3.z);
    acc.w = (a0.w + a1.w) + (a2.w + a3.w);
    const float sc = 1.0f / (float)max(e - s, 1);
    __half2 p01 = __float22half2_rn(make_float2(acc.x * sc, acc.y * sc));
    __half2 p23 = __float22half2_rn(make_float2(acc.z * sc, acc.w * sc));
    *reinterpret_cast<uint2*>(AGG + (size_t)n * D + lane * 4) =
        make_uint2(*(uint32_t*)&p01, *(uint32_t*)&p23);
}

// ---------------- launch -----------------------------------------------------
extern "C" void kernel_launch(void* const* d_in, const int* in_sizes, int n_in,
                              void* d_out, int out_size)
{
    const float* x     = (const float*)d_in[0];
    const void*  eidx  =               d_in[1];
    const float* Wm1   = (const float*)d_in[2];
    const float* bm1   = (const float*)d_in[3];
    const float* Wm2   = (const float*)d_in[4];
    const float* bm2   = (const float*)d_in[5];
    const float* Wu1   = (const float*)d_in[6];
    const float* bu1   = (const float*)d_in[7];
    const float* Wu2   = (const float*)d_in[8];
    const float* bu2   = (const float*)d_in[9];
    const float* gamma = (const float*)d_in[10];
    const float* beta  = (const float*)d_in[11];
    float* out = (float*)d_out;

    void *pH1, *pU2, *pY, *pAGG, *pROW, *pCUR, *pEIDX, *pBSUM;
    cudaGetSymbolAddress(&pH1,   g_H1);
    cudaGetSymbolAddress(&pU2,   g_U2);
    cudaGetSymbolAddress(&pY,    g_Y);
    cudaGetSymbolAddress(&pAGG,  g_AGG);
    cudaGetSymbolAddress(&pROW,  g_ROW);
    cudaGetSymbolAddress(&pCUR,  g_CUR);
    cudaGetSymbolAddress(&pEIDX, g_EIDX);
    cudaGetSymbolAddress(&pBSUM, g_BSUM);

    // smem: 512 hdr + A (64x136 half) + B (64x136 half) = 35328 B -> 4 CTAs/SM
    const int SMF = 512 + 2 * (64 * 136 * 2);
    const int GG = 1250;   // 625 m-tiles x 2 n-tiles

    // weights fp16 + CUR zero + dtype sniff, one launch
    prep_kernel <<<320, 256>>>(Wm1, Wm2, Wu1, Wu2, (const int*)eidx, (int*)pCUR);
    count_kernel<<<2500, 256>>>(eidx, (int*)pCUR);
    scanA_kernel<<<40, 1024>>>((const int*)pCUR, (int*)pROW, (int*)pBSUM);
    scanC_kernel<<<40, 1024>>>((int*)pROW, (const int*)pBSUM, (int*)pCUR);
    fill_kernel <<<2500, 256>>>(eidx, (int*)pCUR, (int*)pEIDX);

    // message MLP (per-node, algebraically identical to per-edge)
    gemm64f<128, true,  true,  false, false><<<GG, 256, SMF>>>(
        x, nullptr, 0, bm1, nullptr, (__half*)pH1);
    gemm64f<128, false, true,  true,  false><<<GG, 256, SMF>>>(
        pH1, nullptr, 16384, bm2, nullptr, (__half*)pY);
    // CSR gather-mean over fp16 Y
    gather_kernel<<<5000, 256>>>((const __half*)pY, (const int*)pROW,
                                 (const int*)pEIDX, (__half*)pAGG);
    // update MLP on concat([x, agg])
    gemm64f<256, true,  true,  false, true ><<<GG, 256, SMF>>>(
        x, pAGG, 32768, bu1, nullptr, (__half*)pH1);
    gemm64f<128, false, false, true,  false><<<GG, 256, SMF>>>(
        pH1, nullptr, 65536, bu2, (float*)pU2, nullptr);
    // residual + LayerNorm
    ln_kernel<<<5000, 256>>>((const float*)pU2, x, gamma, beta, out);
}

// round 17
// speedup vs baseline: 1.5611x; 1.0307x over previous
#include <cuda_runtime.h>
#include <cuda_bf16.h>
#include <cuda_fp16.h>
#include <cstdint>

#define N_NODES 40000
#define N_EDGES 640000
#define D 128

// ---------------- scratch (device globals: no allocations allowed) ----------
static __device__ __half g_H1 [N_NODES * D];  // msg hidden, then upd hidden (fp16)
static __device__ __half g_Y  [N_NODES * D];  // per-node message output (fp16)
static __device__ __half g_AGG[N_NODES * D];  // scatter-mean result (fp16)
static __device__ int    g_ROW[N_NODES + 1];  // CSR row offsets (by dst)
static __device__ int    g_CUR[N_NODES];      // counts, then fill cursors
static __device__ int    g_EIDX[N_EDGES];     // src ids grouped by dst
static __device__ int    g_BVAL[64];          // scan block totals
static __device__ int    g_BFLG[64];          // scan publish flags
static __device__ int    g_is64;              // edge_index dtype flag
// pre-converted fp16 weights, [n][k] row-major:
//   Wm1 @ 0 (16384), Wm2 @ 16384, Wu1 @ 32768 (32768), Wu2 @ 65536
static __device__ __half g_Wf[81920];

// ---------------- helpers ----------------------------------------------------
__device__ __forceinline__ uint32_t smem_u32(const void* p) {
    return (uint32_t)__cvta_generic_to_shared(p);
}

#define LDSM_X4(r0, r1, r2, r3, addr) \
    asm volatile("ldmatrix.sync.aligned.m8n8.x4.shared.b16 {%0,%1,%2,%3}, [%4];" \
        : "=r"(r0), "=r"(r1), "=r"(r2), "=r"(r3) : "r"(addr))

#define MMA_F16(c, a, b) \
    asm volatile("mma.sync.aligned.m16n8k16.row.col.f32.f16.f16.f32 " \
        "{%0,%1,%2,%3}, {%4,%5,%6,%7}, {%8,%9}, {%0,%1,%2,%3};" \
        : "+f"((c)[0]), "+f"((c)[1]), "+f"((c)[2]), "+f"((c)[3]) \
        : "r"((a)[0]), "r"((a)[1]), "r"((a)[2]), "r"((a)[3]), \
          "r"((b)[0]), "r"((b)[1]))

// ---------------- N=64-tile fp16 GEMM: single-pass, 4 CTAs/SM ---------------
// C[:, n0:n0+64] = act(concat(A0,A1) @ W^T + bias)[:, n0:n0+64]
// Tile M=64 x N=64, K-chunk 128, 256 thr (8 warps, 2m x 4n, warp tile 32x16).
template <int KT, bool RELU, bool HOUT, bool A0H, bool A1H>
__global__ __launch_bounds__(256, 4)
void gemm64f(const void* __restrict__ A0, const void* __restrict__ A1,
             int woff, const float* __restrict__ bias,
             float* __restrict__ Cf, __half* __restrict__ Ch)
{
    extern __shared__ char smc[];
    float* sbias = (float*)smc;                       // 64 floats
    __half* sA = (__half*)(smc + 512);                // [64][136]
    __half* sB = sA + 64 * 136;                       // [64][136]

    const int tid  = threadIdx.x;
    const int lane = tid & 31;
    const int wid  = tid >> 5;
    const int wm   = (wid >> 2) * 32;        // 0 / 32
    const int wn   = (wid & 3) * 16;         // 0/16/32/48
    const int m0   = (blockIdx.x >> 1) * 64;
    const int n0   = (blockIdx.x & 1) * 64;

    if (tid < 64) sbias[tid] = bias[n0 + tid];

    float c[2][2][4];
    #pragma unroll
    for (int i = 0; i < 2; i++)
        #pragma unroll
        for (int j = 0; j < 2; j++)
            #pragma unroll
            for (int q = 0; q < 4; q++) c[i][j][q] = 0.0f;

    const int a_row = lane & 15, a_kh = (lane >> 4) * 8;
    const int b_row = (lane >> 4) * 8 + (lane & 7);
    const int b_kh  = ((lane >> 3) & 1) * 8;

    const int nchunks = KT / 128;
    #pragma unroll
    for (int kc = 0; kc < nchunks; ++kc) {
        const bool ah16 = (kc == 0) ? A0H : A1H;
        const void* Asrc = (kc == 0) ? A0 : A1;

        if (!ah16) {
            const float* Af = (const float*)Asrc;
            #pragma unroll
            for (int it = 0; it < 8; ++it) {
                int idx  = tid + it * 256;
                int row  = idx >> 5;
                int col4 = idx & 31;
                float4 v = *reinterpret_cast<const float4*>(
                    Af + (size_t)(m0 + row) * D + col4 * 4);
                __half2 h01 = __float22half2_rn(make_float2(v.x, v.y));
                __half2 h23 = __float22half2_rn(make_float2(v.z, v.w));
                *reinterpret_cast<uint2*>(sA + row * 136 + col4 * 4) =
                    make_uint2(*(uint32_t*)&h01, *(uint32_t*)&h23);
            }
        } else {
            const __half* Ah = (const __half*)Asrc;
            #pragma unroll
            for (int it = 0; it < 4; ++it) {
                int idx = tid + it * 256;
                int row = idx >> 4;
                int c8  = idx & 15;
                *reinterpret_cast<uint4*>(sA + row * 136 + c8 * 8) =
                    *reinterpret_cast<const uint4*>(Ah + (size_t)(m0 + row) * D + c8 * 8);
            }
        }
        #pragma unroll
        for (int it = 0; it < 4; ++it) {
            int idx = tid + it * 256;
            int row = idx >> 4;
            int c8  = idx & 15;
            size_t gsrc = (size_t)woff + (size_t)(n0 + row) * KT + kc * 128 + c8 * 8;
            *reinterpret_cast<uint4*>(sB + row * 136 + c8 * 8) =
                *reinterpret_cast<const uint4*>(g_Wf + gsrc);
        }
        __syncthreads();

        #pragma unroll
        for (int ks = 0; ks < 8; ++ks) {
            const int kb = ks * 16;
            uint32_t ah[2][4], bh[2][2];
            #pragma unroll
            for (int mt = 0; mt < 2; ++mt) {
                uint32_t addr = smem_u32(sA + (wm + mt * 16 + a_row) * 136 + kb + a_kh);
                LDSM_X4(ah[mt][0], ah[mt][1], ah[mt][2], ah[mt][3], addr);
            }
            {
                uint32_t addr = smem_u32(sB + (wn + b_row) * 136 + kb + b_kh);
                LDSM_X4(bh[0][0], bh[0][1], bh[1][0], bh[1][1], addr);
            }
            #pragma unroll
            for (int mt = 0; mt < 2; ++mt)
                #pragma unroll
                for (int nt = 0; nt < 2; ++nt)
                    MMA_F16(c[mt][nt], ah[mt], bh[nt]);
        }
        __syncthreads();
    }

    const int g = lane >> 2, cl = (lane & 3) * 2;
    #pragma unroll
    for (int mt = 0; mt < 2; ++mt) {
        const int m = m0 + wm + mt * 16 + g;
        #pragma unroll
        for (int nt = 0; nt < 2; ++nt) {
            const int nl = wn + nt * 8 + cl;
            const int n  = n0 + nl;
            float f0 = c[mt][nt][0] + sbias[nl];
            float f1 = c[mt][nt][1] + sbias[nl + 1];
            float f2 = c[mt][nt][2] + sbias[nl];
            float f3 = c[mt][nt][3] + sbias[nl + 1];
            if (RELU) {
                f0 = fmaxf(f0, 0.f); f1 = fmaxf(f1, 0.f);
                f2 = fmaxf(f2, 0.f); f3 = fmaxf(f3, 0.f);
            }
            if (HOUT) {
                *reinterpret_cast<__half2*>(Ch + (size_t)m * D + n) =
                    __float22half2_rn(make_float2(f0, f1));
                *reinterpret_cast<__half2*>(Ch + (size_t)(m + 8) * D + n) =
                    __float22half2_rn(make_float2(f2, f3));
            } else {
                *reinterpret_cast<float2*>(Cf + (size_t)m * D + n)       = make_float2(f0, f1);
                *reinterpret_cast<float2*>(Cf + (size_t)(m + 8) * D + n) = make_float2(f2, f3);
            }
        }
    }
}

// ---------------- final GEMM fused with residual + LayerNorm ----------------
// M=64 x N=128 tile (full rows per block -> in-block LN), K=128, 256 thr,
// warp tile 32x32 (2m x 4n of n8). Proven R9 smem-atomicAdd stats epilogue.
__global__ __launch_bounds__(256, 3)
void updgemm_kernel(const __half* __restrict__ H1, const float* __restrict__ x,
                    const float* __restrict__ bu2, const float* __restrict__ gamma,
                    const float* __restrict__ beta, float* __restrict__ out)
{
    extern __shared__ char smc[];
    float* sb2  = (float*)smc;           // 128
    float* sg   = sb2 + 128;             // 128
    float* sbt  = sg + 128;              // 128
    float* ssum = sbt + 128;             // 64
    float* ssq  = ssum + 64;             // 64
    __half* sA  = (__half*)(smc + 2048); // [64][136]
    __half* sB  = sA + 64 * 136;         // [128][136]

    const int tid  = threadIdx.x;
    const int lane = tid & 31;
    const int wid  = tid >> 5;
    const int wm   = (wid >> 2) * 32;    // 0 / 32
    const int wn   = (wid & 3) * 32;     // 0/32/64/96
    const int m0   = blockIdx.x * 64;

    if (tid < 128) { sb2[tid] = bu2[tid]; sg[tid] = gamma[tid]; sbt[tid] = beta[tid]; }
    if (tid < 64)  { ssum[tid] = 0.f; ssq[tid] = 0.f; }

    // A: copy fp16 H1 rows m0..m0+63
    #pragma unroll
    for (int it = 0; it < 4; ++it) {
        int idx = tid + it * 256;
        int row = idx >> 4;
        int c8  = idx & 15;
        *reinterpret_cast<uint4*>(sA + row * 136 + c8 * 8) =
            *reinterpret_cast<const uint4*>(H1 + (size_t)(m0 + row) * D + c8 * 8);
    }
    // B: Wu2 all 128 rows (woff 65536)
    #pragma unroll
    for (int it = 0; it < 8; ++it) {
        int idx = tid + it * 256;
        int row = idx >> 4;
        int c8  = idx & 15;
        *reinterpret_cast<uint4*>(sB + row * 136 + c8 * 8) =
            *reinterpret_cast<const uint4*>(g_Wf + 65536 + (size_t)row * 128 + c8 * 8);
    }
    __syncthreads();

    float c[2][4][4];
    #pragma unroll
    for (int i = 0; i < 2; i++)
        #pragma unroll
        for (int j = 0; j < 4; j++)
            #pragma unroll
            for (int q = 0; q < 4; q++) c[i][j][q] = 0.0f;

    const int a_row = lane & 15, a_kh = (lane >> 4) * 8;
    const int b_row = (lane >> 4) * 8 + (lane & 7);
    const int b_kh  = ((lane >> 3) & 1) * 8;

    #pragma unroll
    for (int ks = 0; ks < 8; ++ks) {
        const int kb = ks * 16;
        uint32_t ah[2][4], bh[4][2];
        #pragma unroll
        for (int mt = 0; mt < 2; ++mt) {
            uint32_t addr = smem_u32(sA + (wm + mt * 16 + a_row) * 136 + kb + a_kh);
            LDSM_X4(ah[mt][0], ah[mt][1], ah[mt][2], ah[mt][3], addr);
        }
        #pragma unroll
        for (int bt = 0; bt < 2; ++bt) {
            uint32_t addr = smem_u32(sB + (wn + bt * 16 + b_row) * 136 + kb + b_kh);
            LDSM_X4(bh[bt*2][0], bh[bt*2][1], bh[bt*2+1][0], bh[bt*2+1][1], addr);
        }
        #pragma unroll
        for (int mt = 0; mt < 2; ++mt)
            #pragma unroll
            for (int nt = 0; nt < 4; ++nt)
                MMA_F16(c[mt][nt], ah[mt], bh[nt]);
    }
    __syncthreads();

    // h = c + bias + residual(x); keep in c. Row partial sums -> smem.
    const int g = lane >> 2, cl = (lane & 3) * 2;
    #pragma unroll
    for (int mt = 0; mt < 2; ++mt) {
        const int row0 = wm + mt * 16 + g;
        float s0 = 0.f, q0 = 0.f, s1 = 0.f, q1 = 0.f;
        #pragma unroll
        for (int nt = 0; nt < 4; ++nt) {
            const int col = wn + nt * 8 + cl;
            float2 r0 = *reinterpret_cast<const float2*>(x + (size_t)(m0 + row0) * D + col);
            float2 r1 = *reinterpret_cast<const float2*>(x + (size_t)(m0 + row0 + 8) * D + col);
            float h0 = c[mt][nt][0] + sb2[col]     + r0.x;
            float h1 = c[mt][nt][1] + sb2[col + 1] + r0.y;
            float h2 = c[mt][nt][2] + sb2[col]     + r1.x;
            float h3 = c[mt][nt][3] + sb2[col + 1] + r1.y;
            c[mt][nt][0] = h0; c[mt][nt][1] = h1; c[mt][nt][2] = h2; c[mt][nt][3] = h3;
            s0 += h0 + h1; q0 += h0 * h0 + h1 * h1;
            s1 += h2 + h3; q1 += h2 * h2 + h3 * h3;
        }
        #pragma unroll
        for (int o = 1; o <= 2; o <<= 1) {
            s0 += __shfl_xor_sync(0xffffffffu, s0, o);
            q0 += __shfl_xor_sync(0xffffffffu, q0, o);
            s1 += __shfl_xor_sync(0xffffffffu, s1, o);
            q1 += __shfl_xor_sync(0xffffffffu, q1, o);
        }
        if ((lane & 3) == 0) {
            atomicAdd(&ssum[row0], s0);     atomicAdd(&ssq[row0], q0);
            atomicAdd(&ssum[row0 + 8], s1); atomicAdd(&ssq[row0 + 8], q1);
        }
    }
    __syncthreads();

    #pragma unroll
    for (int mt = 0; mt < 2; ++mt) {
        const int row0 = wm + mt * 16 + g;
        float mu0 = ssum[row0] * (1.f / 128.f);
        float v0  = ssq[row0] * (1.f / 128.f) - mu0 * mu0;
        float rs0 = rsqrtf(v0 + 1e-5f);
        float mu1 = ssum[row0 + 8] * (1.f / 128.f);
        float v1  = ssq[row0 + 8] * (1.f / 128.f) - mu1 * mu1;
        float rs1 = rsqrtf(v1 + 1e-5f);
        #pragma unroll
        for (int nt = 0; nt < 4; ++nt) {
            const int col = wn + nt * 8 + cl;
            float2 o0, o1;
            o0.x = (c[mt][nt][0] - mu0) * rs0 * sg[col]     + sbt[col];
            o0.y = (c[mt][nt][1] - mu0) * rs0 * sg[col + 1] + sbt[col + 1];
            o1.x = (c[mt][nt][2] - mu1) * rs1 * sg[col]     + sbt[col];
            o1.y = (c[mt][nt][3] - mu1) * rs1 * sg[col + 1] + sbt[col + 1];
            *reinterpret_cast<float2*>(out + (size_t)(m0 + row0) * D + col)     = o0;
            *reinterpret_cast<float2*>(out + (size_t)(m0 + row0 + 8) * D + col) = o1;
        }
    }
}

// ---------------- weight fp16 convert + CUR/flag zero + dtype sniff ---------
__global__ void prep_kernel(const float* __restrict__ Wm1, const float* __restrict__ Wm2,
                            const float* __restrict__ Wu1, const float* __restrict__ Wu2,
                            const int* __restrict__ e, int* __restrict__ CUR)
{
    int i = blockIdx.x * blockDim.x + threadIdx.x;
    if (i < N_NODES) CUR[i] = 0;
    if (i < 64) g_BFLG[i] = 0;
    if (blockIdx.x == 0 && threadIdx.x < 32) {
        // int64 values < 2^31 viewed as int32 have every odd slot == 0
        int any = 0;
        #pragma unroll
        for (int j = 0; j < 4; j++) any |= e[1 + 2 * (threadIdx.x * 4 + j)];
        int found = __any_sync(0xffffffffu, any != 0);
        if (threadIdx.x == 0) g_is64 = found ? 0 : 1;
    }
    if (i < 81920) {
        float f;
        if      (i < 16384) f = Wm1[i];
        else if (i < 32768) f = Wm2[i - 16384];
        else if (i < 65536) f = Wu1[i - 32768];
        else                f = Wu2[i - 65536];
        g_Wf[i] = __float2half_rn(f);
    }
}

// ---------------- CSR build ---------------------------------------------------
__global__ void count_kernel(const void* __restrict__ eidx, int* __restrict__ CUR) {
    int e = blockIdx.x * blockDim.x + threadIdx.x;     // 2500*256 = E exact
    int dst = g_is64 ? (int)reinterpret_cast<const long long*>(eidx)[N_EDGES + e]
                     : reinterpret_cast<const int*>(eidx)[N_EDGES + e];
    atomicAdd(&CUR[dst], 1);
}
// single-pass scan with decoupled lookback: 40 blocks (all resident).
__global__ void scan_kernel(const int* __restrict__ CUR, int* __restrict__ ROW,
                            int* __restrict__ CUR2) {
    __shared__ int s[1024];
    __shared__ int spred[40];
    __shared__ int soff;
    const int t = threadIdx.x;
    const int b = blockIdx.x;
    const int i = b * 1024 + t;
    int v = (i < N_NODES) ? CUR[i] : 0;
    s[t] = v;
    __syncthreads();
    for (int off = 1; off < 1024; off <<= 1) {
        int tmp = (t >= off) ? s[t - off] : 0;
        __syncthreads();
        s[t] += tmp;
        __syncthreads();
    }
    // publish this block's total
    if (t == 1023) {
        g_BVAL[b] = s[1023];
        __threadfence();
        atomicExch(&g_BFLG[b], 1);
    }
    // parallel lookback: thread t (< b) waits for predecessor t
    if (t < b) {
        while (atomicAdd(&g_BFLG[t], 0) == 0) { }
        spred[t] = g_BVAL[t];
    }
    __syncthreads();
    if (t == 0) {
        int run = 0;
        for (int p = 0; p < b; p++) run += spred[p];
        soff = run;
        if (b == 0) ROW[N_NODES] = N_EDGES;
    }
    __syncthreads();
    if (i < N_NODES) {
        int r = s[t] - v + soff;   // global exclusive
        ROW[i]  = r;
        CUR2[i] = r;               // cursor for fill
    }
}
__global__ void fill_kernel(const void* __restrict__ eidx, int* __restrict__ CUR,
                            int* __restrict__ EIDX) {
    int e = blockIdx.x * blockDim.x + threadIdx.x;
    int src, dst;
    if (g_is64) {
        const long long* p = reinterpret_cast<const long long*>(eidx);
        src = (int)p[e]; dst = (int)p[N_EDGES + e];
    } else {
        const int* p = reinterpret_cast<const int*>(eidx);
        src = p[e]; dst = p[N_EDGES + e];
    }
    int pos = atomicAdd(&CUR[dst], 1);
    EIDX[pos] = src;
}
// one warp per node: sum fp16 Y[src] over incoming edges, divide by degree.
__global__ void gather_kernel(const __half* __restrict__ Y, const int* __restrict__ ROW,
                              const int* __restrict__ EIDX, __half* __restrict__ AGG) {
    const int n    = blockIdx.x * 8 + (threadIdx.x >> 5);
    const int lane = threadIdx.x & 31;
    const int s = ROW[n], e = ROW[n + 1];
    float4 a0 = make_float4(0.f, 0.f, 0.f, 0.f);
    float4 a1 = make_float4(0.f, 0.f, 0.f, 0.f);
    float4 a2 = make_float4(0.f, 0.f, 0.f, 0.f);
    float4 a3 = make_float4(0.f, 0.f, 0.f, 0.f);
    for (int base = s; base < e; base += 32) {
        const int cnt = min(32, e - base);
        int idx = (base + lane < e) ? EIDX[base + lane] : 0;
        int j = 0;
        for (; j + 4 <= cnt; j += 4) {
            int s0 = __shfl_sync(0xffffffffu, idx, j);
            int s1 = __shfl_sync(0xffffffffu, idx, j + 1);
            int s2 = __shfl_sync(0xffffffffu, idx, j + 2);
            int s3 = __shfl_sync(0xffffffffu, idx, j + 3);
            uint2 r0 = *reinterpret_cast<const uint2*>(Y + (size_t)s0 * D + lane * 4);
            uint2 r1 = *reinterpret_cast<const uint2*>(Y + (size_t)s1 * D + lane * 4);
            uint2 r2 = *reinterpret_cast<const uint2*>(Y + (size_t)s2 * D + lane * 4);
            uint2 r3 = *reinterpret_cast<const uint2*>(Y + (size_t)s3 * D + lane * 4);
            float2 f;
            f = __half22float2(*(__half2*)&r0.x); a0.x += f.x; a0.y += f.y;
            f = __half22float2(*(__half2*)&r0.y); a0.z += f.x; a0.w += f.y;
            f = __half22float2(*(__half2*)&r1.x); a1.x += f.x; a1.y += f.y;
            f = __half22float2(*(__half2*)&r1.y); a1.z += f.x; a1.w += f.y;
            f = __half22float2(*(__half2*)&r2.x); a2.x += f.x; a2.y += f.y;
            f = __half22float2(*(__half2*)&r2.y); a2.z += f.x; a2.w += f.y;
            f = __half22float2(*(__half2*)&r3.x); a3.x += f.x; a3.y += f.y;
            f = __half22float2(*(__half2*)&r3.y); a3.z += f.x; a3.w += f.y;
        }
        for (; j < cnt; ++j) {
            int s0 = __shfl_sync(0xffffffffu, idx, j);
            uint2 r0 = *reinterpret_cast<const uint2*>(Y + (size_t)s0 * D + lane * 4);
            float2 f;
            f = __half22float2(*(__half2*)&r0.x); a0.x += f.x; a0.y += f.y;
            f = __half22float2(*(__half2*)&r0.y); a0.z += f.x; a0.w += f.y;
        }
    }
    float4 acc;
    acc.x = (a0.x + a1.x) + (a2.x + a3.x);
    acc.y = (a0.y + a1.y) + (a2.y + a3.y);
    acc.z = (a0.z + a1.z) + (a2.z + a3.z);
    acc.w = (a0.w + a1.w) + (a2.w + a3.w);
    const float sc = 1.0f / (float)max(e - s, 1);
    __half2 p01 = __float22half2_rn(make_float2(acc.x * sc, acc.y * sc));
    __half2 p23 = __float22half2_rn(make_float2(acc.z * sc, acc.w * sc));
    *reinterpret_cast<uint2*>(AGG + (size_t)n * D + lane * 4) =
        make_uint2(*(uint32_t*)&p01, *(uint32_t*)&p23);
}

// ---------------- launch -----------------------------------------------------
extern "C" void kernel_launch(void* const* d_in, const int* in_sizes, int n_in,
                              void* d_out, int out_size)
{
    const float* x     = (const float*)d_in[0];
    const void*  eidx  =               d_in[1];
    const float* Wm1   = (const float*)d_in[2];
    const float* bm1   = (const float*)d_in[3];
    const float* Wm2   = (const float*)d_in[4];
    const float* bm2   = (const float*)d_in[5];
    const float* Wu1   = (const float*)d_in[6];
    const float* bu1   = (const float*)d_in[7];
    const float* Wu2   = (const float*)d_in[8];
    const float* bu2   = (const float*)d_in[9];
    const float* gamma = (const float*)d_in[10];
    const float* beta  = (const float*)d_in[11];
    float* out = (float*)d_out;
    (void)Wu2;

    void *pH1, *pY, *pAGG, *pROW, *pCUR, *pEIDX;
    cudaGetSymbolAddress(&pH1,   g_H1);
    cudaGetSymbolAddress(&pY,    g_Y);
    cudaGetSymbolAddress(&pAGG,  g_AGG);
    cudaGetSymbolAddress(&pROW,  g_ROW);
    cudaGetSymbolAddress(&pCUR,  g_CUR);
    cudaGetSymbolAddress(&pEIDX, g_EIDX);

    // gemm64f smem: 512 + 2*(64*136*2) = 35328 (<48K default)
    const int SMF = 512 + 2 * (64 * 136 * 2);
    // updgemm smem: 2048 + 64*136*2 + 128*136*2 = 54272 (>48K)
    const int SMU = 2048 + 64 * 136 * 2 + 128 * 136 * 2;
    cudaFuncSetAttribute(updgemm_kernel, cudaFuncAttributeMaxDynamicSharedMemorySize, SMU);

    const int GG = 1250;   // 625 m-tiles x 2 n-tiles

    prep_kernel <<<320, 256>>>(Wm1, Wm2, Wu1, Wu2, (const int*)eidx, (int*)pCUR);
    count_kernel<<<2500, 256>>>(eidx, (int*)pCUR);
    scan_kernel <<<40, 1024>>>((const int*)pCUR, (int*)pROW, (int*)pCUR);
    fill_kernel <<<2500, 256>>>(eidx, (int*)pCUR, (int*)pEIDX);

    // message MLP (per-node, algebraically identical to per-edge)
    gemm64f<128, true,  true,  false, false><<<GG, 256, SMF>>>(
        x, nullptr, 0, bm1, nullptr, (__half*)pH1);
    gemm64f<128, false, true,  true,  false><<<GG, 256, SMF>>>(
        pH1, nullptr, 16384, bm2, nullptr, (__half*)pY);
    // CSR gather-mean over fp16 Y
    gather_kernel<<<5000, 256>>>((const __half*)pY, (const int*)pROW,
                                 (const int*)pEIDX, (__half*)pAGG);
    // update MLP on concat([x, agg])
    gemm64f<256, true,  true,  false, true ><<<GG, 256, SMF>>>(
        x, pAGG, 32768, bu1, nullptr, (__half*)pH1);
    // final GEMM + residual + LayerNorm fused
    updgemm_kernel<<<625, 256, SMU>>>((const __half*)pH1, x, bu2, gamma, beta, out);
}